// round 9
// baseline (speedup 1.0000x reference)
#include <cuda_runtime.h>
#include <math.h>

#define NIMG 4
#define NCLS 19
#define HWPIX 589824            // 768*768
#define NTOT (NIMG * HWPIX)
#define IGN 255
#define EDGE_T 0.8f
#define PPT 8                   // pixels per thread
#define TPB 256
#define BPI (HWPIX / (TPB * PPT))   // 288 blocks per image
#define GRID (NIMG * BPI)           // 1152
#define INVC 31                 // "invalid" class sentinel (never matches 0..18)

// ---------------- device-global scratch (no allocations allowed) ----------------
// Zero-initialized at module load (covers the first correctness call);
// the last block resets everything after producing the output so each graph
// replay starts clean.
__device__ double g_seg_sum[NIMG * NCLS];
__device__ double g_att_sum[NIMG * NCLS];
__device__ int    g_seg_cnt[NIMG * NCLS];
__device__ int    g_att_cnt[NIMG * NCLS];
__device__ double g_bce_pos, g_bce_neg;
__device__ int    g_pos, g_neg;
__device__ unsigned g_done;

// ---------------- single fused kernel ----------------
__global__ void __launch_bounds__(TPB, 4) k_fused(const float* __restrict__ segin,
                                                  const float* __restrict__ edgein,
                                                  const int* __restrict__ segmask,
                                                  const int* __restrict__ emask,
                                                  float* __restrict__ out) {
    int n   = blockIdx.x / BPI;
    int tid = threadIdx.x;
    int wid = tid >> 5;
    int lid = tid & 31;

    int local = (blockIdx.x % BPI) * (TPB * PPT) + tid * PPT;
    int p     = n * HWPIX + local;

    // ---- prologue: consume all mask/edge data NOW so it doesn't stay live ----
    int4   t0 = *(const int4*)(segmask + p);
    int4   t1 = *(const int4*)(segmask + p + 4);
    float4 e0 = *(const float4*)(edgein + p);
    float4 e1 = *(const float4*)(edgein + p + 4);
    int4   m0 = *(const int4*)(emask + p);
    int4   m1 = *(const int4*)(emask + p + 4);

    int   tv[PPT] = {t0.x, t0.y, t0.z, t0.w, t1.x, t1.y, t1.z, t1.w};
    float ev[PPT] = {e0.x, e0.y, e0.z, e0.w, e1.x, e1.y, e1.z, e1.w};
    int   mv[PPT] = {m0.x, m0.y, m0.z, m0.w, m1.x, m1.y, m1.z, m1.w};

    int tcls[PPT];               // class for select; INVC for ignored pixels
    unsigned attb = 0u;          // att flag bit per pixel
    float bce_p = 0.f, bce_n = 0.f;
    unsigned pn = 0;             // pos lo16, neg hi16
#pragma unroll
    for (int i = 0; i < PPT; i++) {
        bool v  = (tv[i] != IGN);
        tcls[i] = v ? min(max(tv[i], 0), NCLS - 1) : INVC;
        if (v && (ev[i] > EDGE_T)) attb |= (1u << i);

        float xx = ev[i];
        float b  = fmaxf(xx, 0.f) - xx * (float)mv[i] + log1pf(__expf(-fabsf(xx)));
        if (mv[i] == 1) { bce_p += b; pn += 1u; }
        else if (mv[i] == 0) { bce_n += b; pn += 0x10000u; }
    }
    // tv/ev/mv dead here -> registers freed for the sweep

    // ---- channel sweep: online sum-exp + target-logit select ----
    const float* sp = segin + (size_t)n * (size_t)NCLS * (size_t)HWPIX + (size_t)local;

    float s[PPT], xt[PPT];
#pragma unroll
    for (int i = 0; i < PPT; i++) { s[i] = 0.f; xt[i] = 0.f; }

#pragma unroll
    for (int c0 = 0; c0 < NCLS; c0 += 4) {
        float4 a[4][2];
#pragma unroll
        for (int j = 0; j < 4; j++) {
            int c = c0 + j;
            if (c < NCLS) {
                a[j][0] = *(const float4*)(sp + (size_t)c * HWPIX);
                a[j][1] = *(const float4*)(sp + (size_t)c * HWPIX + 4);
            }
        }
#pragma unroll
        for (int j = 0; j < 4; j++) {
            int c = c0 + j;
            if (c < NCLS) {
                float xv[PPT] = {a[j][0].x, a[j][0].y, a[j][0].z, a[j][0].w,
                                 a[j][1].x, a[j][1].y, a[j][1].z, a[j][1].w};
#pragma unroll
                for (int i = 0; i < PPT; i++) {
                    s[i] += __expf(xv[i]);
                    xt[i] = (c == tcls[i]) ? xv[i] : xt[i];
                }
            }
        }
    }

    // ---- per-pixel nll ----
    float nll[PPT], nllA[PPT];
    unsigned addC[PPT];
#pragma unroll
    for (int i = 0; i < PPT; i++) {
        nll[i]  = __logf(s[i]) - xt[i];          // -log_softmax[target]
        bool a  = (attb >> i) & 1u;
        nllA[i] = a ? nll[i] : 0.f;
        addC[i] = a ? 0x10001u : 1u;             // att count hi16, seg count lo16
    }

    // ---- per-class register select + warp/block reduction ----
    __shared__ float sh_ss[NCLS][8];
    __shared__ float sh_sa[NCLS][8];
    __shared__ unsigned sh_cc[NCLS][8];
    __shared__ float sh_bp[8], sh_bn[8];
    __shared__ unsigned sh_pn[8];

#pragma unroll
    for (int c = 0; c < NCLS; c++) {
        float ss = 0.f, sa = 0.f;
        unsigned cc = 0u;
#pragma unroll
        for (int i = 0; i < PPT; i++) {
            if (tcls[i] == c) { ss += nll[i]; sa += nllA[i]; cc += addC[i]; }
        }
        for (int o = 16; o; o >>= 1) {
            ss += __shfl_down_sync(0xffffffffu, ss, o);
            sa += __shfl_down_sync(0xffffffffu, sa, o);
        }
        cc = __reduce_add_sync(0xffffffffu, cc);
        if (lid == 0) { sh_ss[c][wid] = ss; sh_sa[c][wid] = sa; sh_cc[c][wid] = cc; }
    }
    for (int o = 16; o; o >>= 1) {
        bce_p += __shfl_down_sync(0xffffffffu, bce_p, o);
        bce_n += __shfl_down_sync(0xffffffffu, bce_n, o);
    }
    pn = __reduce_add_sync(0xffffffffu, pn);
    if (lid == 0) { sh_bp[wid] = bce_p; sh_bn[wid] = bce_n; sh_pn[wid] = pn; }
    __syncthreads();

    if (tid < NCLS) {
        float ss = 0.f, sa = 0.f; unsigned cc = 0u;
#pragma unroll
        for (int w = 0; w < 8; w++) { ss += sh_ss[tid][w]; sa += sh_sa[tid][w]; cc += sh_cc[tid][w]; }
        int gi = n * NCLS + tid;
        atomicAdd(&g_seg_sum[gi], (double)ss);
        atomicAdd(&g_att_sum[gi], (double)sa);
        atomicAdd(&g_seg_cnt[gi], (int)(cc & 0xffffu));
        atomicAdd(&g_att_cnt[gi], (int)(cc >> 16));
    } else if (tid == 32) {
        float bp = 0.f, bn = 0.f; unsigned c = 0u;
#pragma unroll
        for (int w = 0; w < 8; w++) { bp += sh_bp[w]; bn += sh_bn[w]; c += sh_pn[w]; }
        atomicAdd(&g_bce_pos, (double)bp);
        atomicAdd(&g_bce_neg, (double)bn);
        atomicAdd(&g_pos, (int)(c & 0xffffu));
        atomicAdd(&g_neg, (int)(c >> 16));
    }

    // ---- fan-in: last block finalizes ----
    __syncthreads();
    __shared__ unsigned s_last;
    if (tid == 0) {
        __threadfence();
        s_last = (atomicAdd(&g_done, 1u) == GRID - 1u);
    }
    __syncthreads();
    if (!s_last) return;
    __threadfence();   // acquire: make all blocks' g_* writes visible

    // ---------------- finalize (parallel, division-light) ----------------
    __shared__ double f_ss[NIMG * NCLS], f_as[NIMG * NCLS];
    __shared__ int    f_sc[NIMG * NCLS], f_ac[NIMG * NCLS];
    __shared__ double f_rs[NIMG], f_ra[NIMG];
    __shared__ double f_t[NIMG * NCLS][4];
    __shared__ double f_img[NIMG][2];
    __shared__ double f_bce[2];
    __shared__ int    f_pn[2];

    if (tid < NIMG * NCLS) {
        f_ss[tid] = g_seg_sum[tid];
        f_as[tid] = g_att_sum[tid];
        f_sc[tid] = g_seg_cnt[tid];
        f_ac[tid] = g_att_cnt[tid];
    }
    if (tid == 96) { f_bce[0] = g_bce_pos; f_bce[1] = g_bce_neg; }
    if (tid == 97) { f_pn[0] = g_pos; f_pn[1] = g_neg; }
    __syncthreads();

    if (tid < NIMG) {
        int ssum = 0, asum = 0;
#pragma unroll
        for (int c = 0; c < NCLS; c++) { ssum += f_sc[tid * NCLS + c]; asum += f_ac[tid * NCLS + c]; }
        f_rs[tid] = 1.0 / (double)ssum;
        f_ra[tid] = 1.0 / (double)asum;
    }
    __syncthreads();

    if (tid < NIMG * NCLS) {
        int nimg = tid / NCLS;
        int sc = f_sc[tid], ac = f_ac[tid];
        double ws = sc ? (2.0 - (double)sc * f_rs[nimg]) : 1.0;
        double wa = ac ? (2.0 - (double)ac * f_ra[nimg]) : 1.0;
        f_t[tid][0] = ws * f_ss[tid];
        f_t[tid][1] = ws * (double)sc;
        f_t[tid][2] = wa * f_as[tid];
        f_t[tid][3] = wa * (double)ac;
    }
    __syncthreads();

    if (tid < NIMG) {
        double sn = 0, sd = 0, an = 0, ad = 0;
#pragma unroll
        for (int c = 0; c < NCLS; c++) {
            sn += f_t[tid * NCLS + c][0]; sd += f_t[tid * NCLS + c][1];
            an += f_t[tid * NCLS + c][2]; ad += f_t[tid * NCLS + c][3];
        }
        f_img[tid][0] = sn / sd;
        f_img[tid][1] = an / ad;
    }
    __syncthreads();

    if (tid == 0) {
        double segl = 0.0, attl = 0.0;
#pragma unroll
        for (int nn2 = 0; nn2 < NIMG; nn2++) { segl += f_img[nn2][0]; attl += f_img[nn2][1]; }
        double pp = (double)f_pn[0], nng = (double)f_pn[1], sm = pp + nng;
        double bce = ((nng / sm) * f_bce[0] + (pp / sm) * f_bce[1]) / (double)NTOT;
        out[0] = (float)(segl + 0.3 * bce + 0.1 * attl);
    }

    // reset scratch for next graph replay
    if (tid < NIMG * NCLS) {
        g_seg_sum[tid] = 0.0; g_att_sum[tid] = 0.0;
        g_seg_cnt[tid] = 0;   g_att_cnt[tid] = 0;
    }
    if (tid == 96) { g_bce_pos = 0.0; g_bce_neg = 0.0; }
    if (tid == 97) { g_pos = 0; g_neg = 0; }
    if (tid == 98) g_done = 0u;
}

extern "C" void kernel_launch(void* const* d_in, const int* in_sizes, int n_in,
                              void* d_out, int out_size) {
    const float* segin   = (const float*)d_in[0];
    const float* edgein  = (const float*)d_in[1];
    const int*   segmask = (const int*)d_in[2];
    const int*   emask   = (const int*)d_in[3];

    k_fused<<<GRID, TPB>>>(segin, edgein, segmask, emask, (float*)d_out);
}

// round 10
// speedup vs baseline: 1.0947x; 1.0947x over previous
#include <cuda_runtime.h>
#include <math.h>

#define NIMG 4
#define NCLS 19
#define HWPIX 589824            // 768*768
#define NTOT (NIMG * HWPIX)
#define IGN 255
#define EDGE_T 0.8f
#define PPT 8                   // pixels per thread
#define TPB 256
#define BPI (HWPIX / (TPB * PPT))   // 288 blocks per image
#define GRID (NIMG * BPI)           // 1152
#define INVC 31                 // "invalid" class sentinel (never matches 0..18)

// ---------------- device-global scratch (no allocations allowed) ----------------
__device__ double g_seg_sum[NIMG * NCLS];
__device__ double g_att_sum[NIMG * NCLS];
__device__ int    g_seg_cnt[NIMG * NCLS];
__device__ int    g_att_cnt[NIMG * NCLS];
__device__ double g_bce_pos, g_bce_neg;
__device__ int    g_pos, g_neg;
__device__ unsigned g_done;

// ---------------- single fused kernel ----------------
// NOTE: no min-blocks launch_bounds — R8 proved a reg cap kills MLP here.
__global__ void __launch_bounds__(TPB) k_fused(const float* __restrict__ segin,
                                               const float* __restrict__ edgein,
                                               const int* __restrict__ segmask,
                                               const int* __restrict__ emask,
                                               float* __restrict__ out) {
    int n   = blockIdx.x / BPI;
    int tid = threadIdx.x;
    int wid = tid >> 5;
    int lid = tid & 31;

    int local = (blockIdx.x % BPI) * (TPB * PPT) + tid * PPT;
    int p     = n * HWPIX + local;

    // ---- prologue: consume all mask/edge data up front (frees regs for sweep) ----
    int4   t0 = *(const int4*)(segmask + p);
    int4   t1 = *(const int4*)(segmask + p + 4);
    float4 e0 = *(const float4*)(edgein + p);
    float4 e1 = *(const float4*)(edgein + p + 4);
    int4   m0 = *(const int4*)(emask + p);
    int4   m1 = *(const int4*)(emask + p + 4);

    int   tv[PPT] = {t0.x, t0.y, t0.z, t0.w, t1.x, t1.y, t1.z, t1.w};
    float ev[PPT] = {e0.x, e0.y, e0.z, e0.w, e1.x, e1.y, e1.z, e1.w};
    int   mv[PPT] = {m0.x, m0.y, m0.z, m0.w, m1.x, m1.y, m1.z, m1.w};

    int tcls[PPT];               // class for select; INVC for ignored pixels
    unsigned attb = 0u;          // att flag bit per pixel
    float bce_p = 0.f, bce_n = 0.f;
    unsigned pn = 0;             // pos lo16, neg hi16
#pragma unroll
    for (int i = 0; i < PPT; i++) {
        bool v  = (tv[i] != IGN);
        tcls[i] = v ? min(max(tv[i], 0), NCLS - 1) : INVC;
        if (v && (ev[i] > EDGE_T)) attb |= (1u << i);

        float xx = ev[i];
        float b  = fmaxf(xx, 0.f) - xx * (float)mv[i] + log1pf(__expf(-fabsf(xx)));
        if (mv[i] == 1) { bce_p += b; pn += 1u; }
        else if (mv[i] == 0) { bce_n += b; pn += 0x10000u; }
    }
    // tv/ev/mv dead here

    // ---- channel sweep: ping-pong pipelined (prefetch depth 2 channels) ----
    const float* sp = segin + (size_t)n * (size_t)NCLS * (size_t)HWPIX + (size_t)local;

    float s[PPT], xt[PPT];
#pragma unroll
    for (int i = 0; i < PPT; i++) { s[i] = 0.f; xt[i] = 0.f; }

    float4 buf[2][2];
    buf[0][0] = *(const float4*)(sp);
    buf[0][1] = *(const float4*)(sp + 4);
    buf[1][0] = *(const float4*)(sp + (size_t)HWPIX);
    buf[1][1] = *(const float4*)(sp + (size_t)HWPIX + 4);

#pragma unroll
    for (int c = 0; c < NCLS; c++) {
        float4 x0 = buf[c & 1][0];
        float4 x1 = buf[c & 1][1];
        if (c + 2 < NCLS) {           // issue loads for c+2 before consuming c
            buf[c & 1][0] = *(const float4*)(sp + (size_t)(c + 2) * HWPIX);
            buf[c & 1][1] = *(const float4*)(sp + (size_t)(c + 2) * HWPIX + 4);
        }
        float xv[PPT] = {x0.x, x0.y, x0.z, x0.w, x1.x, x1.y, x1.z, x1.w};
#pragma unroll
        for (int i = 0; i < PPT; i++) {
            s[i] += __expf(xv[i]);
            xt[i] = (c == tcls[i]) ? xv[i] : xt[i];
        }
    }

    // ---- per-pixel nll ----
    float nll[PPT], nllA[PPT];
    unsigned addC[PPT];
#pragma unroll
    for (int i = 0; i < PPT; i++) {
        nll[i]  = __logf(s[i]) - xt[i];          // -log_softmax[target]
        bool a  = (attb >> i) & 1u;
        nllA[i] = a ? nll[i] : 0.f;
        addC[i] = a ? 0x10001u : 1u;             // att count hi16, seg count lo16
    }

    // ---- per-class register select + warp/block reduction ----
    __shared__ float sh_ss[NCLS][8];
    __shared__ float sh_sa[NCLS][8];
    __shared__ unsigned sh_cc[NCLS][8];
    __shared__ float sh_bp[8], sh_bn[8];
    __shared__ unsigned sh_pn[8];

#pragma unroll
    for (int c = 0; c < NCLS; c++) {
        float ss = 0.f, sa = 0.f;
        unsigned cc = 0u;
#pragma unroll
        for (int i = 0; i < PPT; i++) {
            if (tcls[i] == c) { ss += nll[i]; sa += nllA[i]; cc += addC[i]; }
        }
        for (int o = 16; o; o >>= 1) {
            ss += __shfl_down_sync(0xffffffffu, ss, o);
            sa += __shfl_down_sync(0xffffffffu, sa, o);
        }
        cc = __reduce_add_sync(0xffffffffu, cc);
        if (lid == 0) { sh_ss[c][wid] = ss; sh_sa[c][wid] = sa; sh_cc[c][wid] = cc; }
    }
    for (int o = 16; o; o >>= 1) {
        bce_p += __shfl_down_sync(0xffffffffu, bce_p, o);
        bce_n += __shfl_down_sync(0xffffffffu, bce_n, o);
    }
    pn = __reduce_add_sync(0xffffffffu, pn);
    if (lid == 0) { sh_bp[wid] = bce_p; sh_bn[wid] = bce_n; sh_pn[wid] = pn; }
    __syncthreads();

    if (tid < NCLS) {
        float ss = 0.f, sa = 0.f; unsigned cc = 0u;
#pragma unroll
        for (int w = 0; w < 8; w++) { ss += sh_ss[tid][w]; sa += sh_sa[tid][w]; cc += sh_cc[tid][w]; }
        int gi = n * NCLS + tid;
        atomicAdd(&g_seg_sum[gi], (double)ss);
        atomicAdd(&g_att_sum[gi], (double)sa);
        atomicAdd(&g_seg_cnt[gi], (int)(cc & 0xffffu));
        atomicAdd(&g_att_cnt[gi], (int)(cc >> 16));
    } else if (tid == 32) {
        float bp = 0.f, bn = 0.f; unsigned c = 0u;
#pragma unroll
        for (int w = 0; w < 8; w++) { bp += sh_bp[w]; bn += sh_bn[w]; c += sh_pn[w]; }
        atomicAdd(&g_bce_pos, (double)bp);
        atomicAdd(&g_bce_neg, (double)bn);
        atomicAdd(&g_pos, (int)(c & 0xffffu));
        atomicAdd(&g_neg, (int)(c >> 16));
    }

    // ---- fan-in: last block finalizes ----
    __syncthreads();
    __shared__ unsigned s_last;
    if (tid == 0) {
        __threadfence();
        s_last = (atomicAdd(&g_done, 1u) == GRID - 1u);
    }
    __syncthreads();
    if (!s_last) return;
    __threadfence();   // acquire: make all blocks' g_* writes visible

    // ---------------- finalize (parallel, division-light) ----------------
    __shared__ double f_ss[NIMG * NCLS], f_as[NIMG * NCLS];
    __shared__ int    f_sc[NIMG * NCLS], f_ac[NIMG * NCLS];
    __shared__ double f_rs[NIMG], f_ra[NIMG];
    __shared__ double f_t[NIMG * NCLS][4];
    __shared__ double f_img[NIMG][2];
    __shared__ double f_bce[2];
    __shared__ int    f_pn[2];

    if (tid < NIMG * NCLS) {
        f_ss[tid] = g_seg_sum[tid];
        f_as[tid] = g_att_sum[tid];
        f_sc[tid] = g_seg_cnt[tid];
        f_ac[tid] = g_att_cnt[tid];
    }
    if (tid == 96) { f_bce[0] = g_bce_pos; f_bce[1] = g_bce_neg; }
    if (tid == 97) { f_pn[0] = g_pos; f_pn[1] = g_neg; }
    __syncthreads();

    if (tid < NIMG) {
        int ssum = 0, asum = 0;
#pragma unroll
        for (int c = 0; c < NCLS; c++) { ssum += f_sc[tid * NCLS + c]; asum += f_ac[tid * NCLS + c]; }
        f_rs[tid] = 1.0 / (double)ssum;
        f_ra[tid] = 1.0 / (double)asum;
    }
    __syncthreads();

    if (tid < NIMG * NCLS) {
        int nimg = tid / NCLS;
        int sc = f_sc[tid], ac = f_ac[tid];
        double ws = sc ? (2.0 - (double)sc * f_rs[nimg]) : 1.0;
        double wa = ac ? (2.0 - (double)ac * f_ra[nimg]) : 1.0;
        f_t[tid][0] = ws * f_ss[tid];
        f_t[tid][1] = ws * (double)sc;
        f_t[tid][2] = wa * f_as[tid];
        f_t[tid][3] = wa * (double)ac;
    }
    __syncthreads();

    if (tid < NIMG) {
        double sn = 0, sd = 0, an = 0, ad = 0;
#pragma unroll
        for (int c = 0; c < NCLS; c++) {
            sn += f_t[tid * NCLS + c][0]; sd += f_t[tid * NCLS + c][1];
            an += f_t[tid * NCLS + c][2]; ad += f_t[tid * NCLS + c][3];
        }
        f_img[tid][0] = sn / sd;
        f_img[tid][1] = an / ad;
    }
    __syncthreads();

    if (tid == 0) {
        double segl = 0.0, attl = 0.0;
#pragma unroll
        for (int nn2 = 0; nn2 < NIMG; nn2++) { segl += f_img[nn2][0]; attl += f_img[nn2][1]; }
        double pp = (double)f_pn[0], nng = (double)f_pn[1], sm = pp + nng;
        double bce = ((nng / sm) * f_bce[0] + (pp / sm) * f_bce[1]) / (double)NTOT;
        out[0] = (float)(segl + 0.3 * bce + 0.1 * attl);
    }

    // reset scratch for next graph replay
    if (tid < NIMG * NCLS) {
        g_seg_sum[tid] = 0.0; g_att_sum[tid] = 0.0;
        g_seg_cnt[tid] = 0;   g_att_cnt[tid] = 0;
    }
    if (tid == 96) { g_bce_pos = 0.0; g_bce_neg = 0.0; }
    if (tid == 97) { g_pos = 0; g_neg = 0; }
    if (tid == 98) g_done = 0u;
}

extern "C" void kernel_launch(void* const* d_in, const int* in_sizes, int n_in,
                              void* d_out, int out_size) {
    const float* segin   = (const float*)d_in[0];
    const float* edgein  = (const float*)d_in[1];
    const int*   segmask = (const int*)d_in[2];
    const int*   emask   = (const int*)d_in[3];

    k_fused<<<GRID, TPB>>>(segin, edgein, segmask, emask, (float*)d_out);
}

// round 11
// speedup vs baseline: 1.2661x; 1.1565x over previous
#include <cuda_runtime.h>
#include <cuda_pipeline.h>
#include <math.h>

#define NIMG 4
#define NCLS 19
#define HWPIX 589824            // 768*768
#define NTOT (NIMG * HWPIX)
#define IGN 255
#define EDGE_T 0.8f
#define PPT 4                   // pixels per thread (R1's best-measured config)
#define TPB 256
#define BPI (HWPIX / (TPB * PPT))   // 576 blocks per image
#define GRID (NIMG * BPI)           // 2304
#define INVC 31                 // "invalid" class sentinel (never matches 0..18)
#define PDEPTH 6                // cp.async prefetch depth (channels)

// ---------------- device-global scratch (no allocations allowed) ----------------
__device__ double g_seg_sum[NIMG * NCLS];
__device__ double g_att_sum[NIMG * NCLS];
__device__ int    g_seg_cnt[NIMG * NCLS];
__device__ int    g_att_cnt[NIMG * NCLS];
__device__ double g_bce_pos, g_bce_neg;
__device__ int    g_pos, g_neg;
__device__ unsigned g_done;

// ---------------- single fused kernel ----------------
// cp.async SMEM ring decouples the segin stream from the exp/select consumer:
// in-flight copies hold no registers, so the DRAM queue stays full while the
// FMA/MUFU pipes chew on already-landed channels.
__global__ void __launch_bounds__(TPB) k_fused(const float* __restrict__ segin,
                                               const float* __restrict__ edgein,
                                               const int* __restrict__ segmask,
                                               const int* __restrict__ emask,
                                               float* __restrict__ out) {
    __shared__ float4 pbuf[PDEPTH][TPB];     // 24 KB prefetch ring (per-thread slots)

    int n   = blockIdx.x / BPI;
    int tid = threadIdx.x;
    int wid = tid >> 5;
    int lid = tid & 31;

    int local = (blockIdx.x % BPI) * (TPB * PPT) + tid * PPT;
    int p     = n * HWPIX + local;

    const float* sp = segin + (size_t)n * (size_t)NCLS * (size_t)HWPIX + (size_t)local;

    // kick off the segin pipeline FIRST so DRAM is busy during the prologue
#pragma unroll
    for (int c = 0; c < PDEPTH; c++) {
        __pipeline_memcpy_async(&pbuf[c][tid], sp + (size_t)c * HWPIX, 16);
        __pipeline_commit();
    }

    // ---- prologue: masks + BCE (consumed immediately; regs freed for sweep) ----
    int4   t4 = *(const int4*)(segmask + p);
    float4 e4 = *(const float4*)(edgein + p);
    int4   m4 = *(const int4*)(emask + p);

    int   tv[PPT] = {t4.x, t4.y, t4.z, t4.w};
    float ev[PPT] = {e4.x, e4.y, e4.z, e4.w};
    int   mv[PPT] = {m4.x, m4.y, m4.z, m4.w};

    int tcls[PPT];               // class for select; INVC for ignored pixels
    unsigned attb = 0u;
    float bce_p = 0.f, bce_n = 0.f;
    unsigned pn = 0;             // pos lo16, neg hi16
#pragma unroll
    for (int i = 0; i < PPT; i++) {
        bool v  = (tv[i] != IGN);
        tcls[i] = v ? min(max(tv[i], 0), NCLS - 1) : INVC;
        if (v && (ev[i] > EDGE_T)) attb |= (1u << i);

        float xx = ev[i];
        float b  = fmaxf(xx, 0.f) - xx * (float)mv[i] + log1pf(__expf(-fabsf(xx)));
        if (mv[i] == 1) { bce_p += b; pn += 1u; }
        else if (mv[i] == 0) { bce_n += b; pn += 0x10000u; }
    }

    // ---- channel sweep out of the SMEM ring ----
    float s[PPT], xt[PPT];
#pragma unroll
    for (int i = 0; i < PPT; i++) { s[i] = 0.f; xt[i] = 0.f; }

#pragma unroll
    for (int c = 0; c < NCLS; c++) {
        __pipeline_wait_prior(PDEPTH - 1);        // channel c's copy has landed
        float4 x = pbuf[c % PDEPTH][tid];
        int cn = c + PDEPTH;
        if (cn < NCLS)
            __pipeline_memcpy_async(&pbuf[c % PDEPTH][tid], sp + (size_t)cn * HWPIX, 16);
        __pipeline_commit();                      // keep group numbering uniform

        float xv[PPT] = {x.x, x.y, x.z, x.w};
#pragma unroll
        for (int i = 0; i < PPT; i++) {
            s[i] += __expf(xv[i]);
            xt[i] = (c == tcls[i]) ? xv[i] : xt[i];
        }
    }

    // ---- per-pixel nll ----
    float nll[PPT], nllA[PPT];
    unsigned addC[PPT];
#pragma unroll
    for (int i = 0; i < PPT; i++) {
        nll[i]  = __logf(s[i]) - xt[i];          // -log_softmax[target]
        bool a  = (attb >> i) & 1u;
        nllA[i] = a ? nll[i] : 0.f;
        addC[i] = a ? 0x10001u : 1u;             // att cnt hi16, seg cnt lo16
    }

    // ---- per-class register select + warp/block reduction ----
    __shared__ float sh_ss[NCLS][8];
    __shared__ float sh_sa[NCLS][8];
    __shared__ unsigned sh_cc[NCLS][8];
    __shared__ float sh_bp[8], sh_bn[8];
    __shared__ unsigned sh_pn[8];

#pragma unroll
    for (int c = 0; c < NCLS; c++) {
        float ss = 0.f, sa = 0.f;
        unsigned cc = 0u;
#pragma unroll
        for (int i = 0; i < PPT; i++) {
            if (tcls[i] == c) { ss += nll[i]; sa += nllA[i]; cc += addC[i]; }
        }
        for (int o = 16; o; o >>= 1) {
            ss += __shfl_down_sync(0xffffffffu, ss, o);
            sa += __shfl_down_sync(0xffffffffu, sa, o);
        }
        cc = __reduce_add_sync(0xffffffffu, cc);
        if (lid == 0) { sh_ss[c][wid] = ss; sh_sa[c][wid] = sa; sh_cc[c][wid] = cc; }
    }
    for (int o = 16; o; o >>= 1) {
        bce_p += __shfl_down_sync(0xffffffffu, bce_p, o);
        bce_n += __shfl_down_sync(0xffffffffu, bce_n, o);
    }
    pn = __reduce_add_sync(0xffffffffu, pn);
    if (lid == 0) { sh_bp[wid] = bce_p; sh_bn[wid] = bce_n; sh_pn[wid] = pn; }
    __syncthreads();

    if (tid < NCLS) {
        float ss = 0.f, sa = 0.f; unsigned cc = 0u;
#pragma unroll
        for (int w = 0; w < 8; w++) { ss += sh_ss[tid][w]; sa += sh_sa[tid][w]; cc += sh_cc[tid][w]; }
        int gi = n * NCLS + tid;
        atomicAdd(&g_seg_sum[gi], (double)ss);
        atomicAdd(&g_att_sum[gi], (double)sa);
        atomicAdd(&g_seg_cnt[gi], (int)(cc & 0xffffu));
        atomicAdd(&g_att_cnt[gi], (int)(cc >> 16));
    } else if (tid == 32) {
        float bp = 0.f, bn = 0.f; unsigned c = 0u;
#pragma unroll
        for (int w = 0; w < 8; w++) { bp += sh_bp[w]; bn += sh_bn[w]; c += sh_pn[w]; }
        atomicAdd(&g_bce_pos, (double)bp);
        atomicAdd(&g_bce_neg, (double)bn);
        atomicAdd(&g_pos, (int)(c & 0xffffu));
        atomicAdd(&g_neg, (int)(c >> 16));
    }

    // ---- fan-in: last block finalizes ----
    __syncthreads();
    __shared__ unsigned s_last;
    if (tid == 0) {
        __threadfence();
        s_last = (atomicAdd(&g_done, 1u) == GRID - 1u);
    }
    __syncthreads();
    if (!s_last) return;
    __threadfence();   // acquire: make all blocks' g_* writes visible

    // ---------------- finalize (parallel, division-light) ----------------
    __shared__ double f_ss[NIMG * NCLS], f_as[NIMG * NCLS];
    __shared__ int    f_sc[NIMG * NCLS], f_ac[NIMG * NCLS];
    __shared__ double f_rs[NIMG], f_ra[NIMG];
    __shared__ double f_t[NIMG * NCLS][4];
    __shared__ double f_img[NIMG][2];
    __shared__ double f_bce[2];
    __shared__ int    f_pn[2];

    if (tid < NIMG * NCLS) {
        f_ss[tid] = g_seg_sum[tid];
        f_as[tid] = g_att_sum[tid];
        f_sc[tid] = g_seg_cnt[tid];
        f_ac[tid] = g_att_cnt[tid];
    }
    if (tid == 96) { f_bce[0] = g_bce_pos; f_bce[1] = g_bce_neg; }
    if (tid == 97) { f_pn[0] = g_pos; f_pn[1] = g_neg; }
    __syncthreads();

    if (tid < NIMG) {
        int ssum = 0, asum = 0;
#pragma unroll
        for (int c = 0; c < NCLS; c++) { ssum += f_sc[tid * NCLS + c]; asum += f_ac[tid * NCLS + c]; }
        f_rs[tid] = 1.0 / (double)ssum;
        f_ra[tid] = 1.0 / (double)asum;
    }
    __syncthreads();

    if (tid < NIMG * NCLS) {
        int nimg = tid / NCLS;
        int sc = f_sc[tid], ac = f_ac[tid];
        double ws = sc ? (2.0 - (double)sc * f_rs[nimg]) : 1.0;
        double wa = ac ? (2.0 - (double)ac * f_ra[nimg]) : 1.0;
        f_t[tid][0] = ws * f_ss[tid];
        f_t[tid][1] = ws * (double)sc;
        f_t[tid][2] = wa * f_as[tid];
        f_t[tid][3] = wa * (double)ac;
    }
    __syncthreads();

    if (tid < NIMG) {
        double sn = 0, sd = 0, an = 0, ad = 0;
#pragma unroll
        for (int c = 0; c < NCLS; c++) {
            sn += f_t[tid * NCLS + c][0]; sd += f_t[tid * NCLS + c][1];
            an += f_t[tid * NCLS + c][2]; ad += f_t[tid * NCLS + c][3];
        }
        f_img[tid][0] = sn / sd;
        f_img[tid][1] = an / ad;
    }
    __syncthreads();

    if (tid == 0) {
        double segl = 0.0, attl = 0.0;
#pragma unroll
        for (int nn2 = 0; nn2 < NIMG; nn2++) { segl += f_img[nn2][0]; attl += f_img[nn2][1]; }
        double pp = (double)f_pn[0], nng = (double)f_pn[1], sm = pp + nng;
        double bce = ((nng / sm) * f_bce[0] + (pp / sm) * f_bce[1]) / (double)NTOT;
        out[0] = (float)(segl + 0.3 * bce + 0.1 * attl);
    }

    // reset scratch for next graph replay
    if (tid < NIMG * NCLS) {
        g_seg_sum[tid] = 0.0; g_att_sum[tid] = 0.0;
        g_seg_cnt[tid] = 0;   g_att_cnt[tid] = 0;
    }
    if (tid == 96) { g_bce_pos = 0.0; g_bce_neg = 0.0; }
    if (tid == 97) { g_pos = 0; g_neg = 0; }
    if (tid == 98) g_done = 0u;
}

extern "C" void kernel_launch(void* const* d_in, const int* in_sizes, int n_in,
                              void* d_out, int out_size) {
    const float* segin   = (const float*)d_in[0];
    const float* edgein  = (const float*)d_in[1];
    const int*   segmask = (const int*)d_in[2];
    const int*   emask   = (const int*)d_in[3];

    k_fused<<<GRID, TPB>>>(segin, edgein, segmask, emask, (float*)d_out);
}